// round 2
// baseline (speedup 1.0000x reference)
#include <cuda_runtime.h>
#include <cuda_bf16.h>

// RoI Align (aligned=False), fixed problem shape:
//   feat (N=8, C=256, H=160, W=160) fp32, rois (K,5) fp32, out (K, 256, 14, 14) fp32
// Reference math simplifies to: ix = fx - 0.5 where fx = (x1 + gx*(x2-x1))*160.
// (aligned=False: ngx = fx/W*2-1; ix = ((ngx+1)*W-1)*0.5 = fx - 0.5 exactly.)

#define NB   8
#define CC   256
#define HH   160
#define WW   160
#define OH   14
#define OW   14
#define CPT  4              // channels per thread
#define CPART (CC / CPT)    // 64

__global__ __launch_bounds__(256)
void DynamicRoIAlign_52913997087012_kernel(
    const float* __restrict__ feat,
    const float* __restrict__ rois,
    float* __restrict__ out,
    int total)
{
    int i = blockIdx.x * blockDim.x + threadIdx.x;
    if (i >= total) return;

    // i -> (k, cp, oy, ox), ox fastest for coalesced stores and x-monotone gathers
    int ox = i % OW;
    int t  = i / OW;
    int oy = t % OH;
    t /= OH;
    int cp = t % CPART;
    int k  = t / CPART;

    // roi: same k across most of a warp -> broadcast / L1 hits
    const float* r = rois + k * 5;
    int   b   = (int)r[0];
    float x1s = r[1] * 160.0f;
    float y1s = r[2] * 160.0f;
    float x2s = r[3] * 160.0f;
    float y2s = r[4] * 160.0f;

    const float inv13 = 1.0f / 13.0f;
    float gx = (float)ox * inv13;
    float gy = (float)oy * inv13;

    float ix = x1s + gx * (x2s - x1s) - 0.5f;
    float iy = y1s + gy * (y2s - y1s) - 0.5f;

    float fx0 = floorf(ix);
    float fy0 = floorf(iy);
    int x0 = (int)fx0;
    int y0 = (int)fy0;
    int x1i = x0 + 1;
    int y1i = y0 + 1;

    float wx1 = ix - fx0, wx0 = 1.0f - wx1;
    float wy1 = iy - fy0, wy0 = 1.0f - wy1;

    float vx0 = (x0  >= 0 && x0  < WW) ? 1.0f : 0.0f;
    float vx1 = (x1i >= 0 && x1i < WW) ? 1.0f : 0.0f;
    float vy0 = (y0  >= 0 && y0  < HH) ? 1.0f : 0.0f;
    float vy1 = (y1i >= 0 && y1i < HH) ? 1.0f : 0.0f;

    int x0c = min(max(x0,  0), WW - 1);
    int x1c = min(max(x1i, 0), WW - 1);
    int y0c = min(max(y0,  0), HH - 1);
    int y1c = min(max(y1i, 0), HH - 1);

    float w00 = wy0 * wx0 * vy0 * vx0;
    float w01 = wy0 * wx1 * vy0 * vx1;
    float w10 = wy1 * wx0 * vy1 * vx0;
    float w11 = wy1 * wx1 * vy1 * vx1;

    int off00 = y0c * WW + x0c;
    int off01 = y0c * WW + x1c;
    int off10 = y1c * WW + x0c;
    int off11 = y1c * WW + x1c;

    const int plane = HH * WW;                       // 25600
    const float* f0 = feat + ((size_t)b * CC + cp) * plane;

    float acc[CPT];
    #pragma unroll
    for (int j = 0; j < CPT; j++) {
        const float* fc = f0 + (size_t)j * CPART * plane;
        float v00 = __ldg(fc + off00);
        float v01 = __ldg(fc + off01);
        float v10 = __ldg(fc + off10);
        float v11 = __ldg(fc + off11);
        acc[j] = w00 * v00 + w01 * v01 + w10 * v10 + w11 * v11;
    }

    float* o = out + ((size_t)k * CC + cp) * (OH * OW) + oy * OW + ox;
    #pragma unroll
    for (int j = 0; j < CPT; j++) {
        o[(size_t)j * CPART * OH * OW] = acc[j];
    }
}

extern "C" void kernel_launch(void* const* d_in, const int* in_sizes, int n_in,
                              void* d_out, int out_size)
{
    const float* feat = (const float*)d_in[0];
    const float* rois = (const float*)d_in[1];
    float* out = (float*)d_out;

    int K = in_sizes[1] / 5;                 // 1024
    int total = K * CPART * OH * OW;         // each thread does CPT channels
    int threads = 256;
    int blocks = (total + threads - 1) / threads;

    DynamicRoIAlign_52913997087012_kernel<<<blocks, threads>>>(feat, rois, out, total);
}

// round 4
// speedup vs baseline: 1.4747x; 1.4747x over previous
#include <cuda_runtime.h>
#include <cuda_bf16.h>

// RoI Align (aligned=False), fixed problem shape:
//   feat (N=8, C=256, H=160, W=160) fp32, rois (K,5) fp32, out (K, 256, 14, 14) fp32
// ix = (x1 + gx*(x2-x1))*160 - 0.5 (aligned=False normalization round-trip cancels).
//
// Counting-sort rois by image id into g_perm so that concurrently scheduled
// blocks all gather from the SAME image plane (26 MB -> L2-resident), collapsing
// DRAM gather traffic to compulsory feat reads. Output is independent of the
// (nondeterministic) within-bin order: every k computes the same values.

#define NB   8
#define CC   256
#define HH   160
#define WW   160
#define OH   14
#define OW   14
#define CPT  4              // channels per thread
#define CPART (CC / CPT)    // 64
#define MAXK 4096

__device__ int g_perm[MAXK];

__global__ void roi_sort_kernel(const float* __restrict__ rois, int K)
{
    __shared__ int offs[NB];
    __shared__ int cnt[NB];
    int tid = threadIdx.x;
    if (tid < NB) cnt[tid] = 0;
    __syncthreads();
    for (int k = tid; k < K; k += blockDim.x) {
        int b = (int)rois[k * 5];
        if (b < 0) b = 0; if (b >= NB) b = NB - 1;
        atomicAdd(&cnt[b], 1);
    }
    __syncthreads();
    if (tid == 0) {
        int s = 0;
        #pragma unroll
        for (int i = 0; i < NB; i++) { offs[i] = s; s += cnt[i]; }
    }
    __syncthreads();
    for (int k = tid; k < K; k += blockDim.x) {
        int b = (int)rois[k * 5];
        if (b < 0) b = 0; if (b >= NB) b = NB - 1;
        int pos = atomicAdd(&offs[b], 1);
        g_perm[pos] = k;
    }
}

__global__ __launch_bounds__(256)
void DynamicRoIAlign_52913997087012_kernel(
    const float* __restrict__ feat,
    const float* __restrict__ rois,
    float* __restrict__ out,
    int total)
{
    int i = blockIdx.x * blockDim.x + threadIdx.x;
    if (i >= total) return;

    // i -> (ksort, cp, oy, ox); ox fastest (coalesced stores, x-monotone gathers);
    // ksort slowest so concurrent blocks share one image's feat plane in L2.
    int ox = i % OW;
    int t  = i / OW;
    int oy = t % OH;
    t /= OH;
    int cp = t % CPART;
    int ksort = t / CPART;

    int k = g_perm[ksort];

    const float* r = rois + k * 5;
    int   b   = (int)r[0];
    float x1s = r[1] * 160.0f;
    float y1s = r[2] * 160.0f;
    float x2s = r[3] * 160.0f;
    float y2s = r[4] * 160.0f;

    const float inv13 = 1.0f / 13.0f;
    float gx = (float)ox * inv13;
    float gy = (float)oy * inv13;

    float ix = x1s + gx * (x2s - x1s) - 0.5f;
    float iy = y1s + gy * (y2s - y1s) - 0.5f;

    float fx0 = floorf(ix);
    float fy0 = floorf(iy);
    int x0 = (int)fx0;
    int y0 = (int)fy0;
    int x1i = x0 + 1;
    int y1i = y0 + 1;

    float wx1 = ix - fx0, wx0 = 1.0f - wx1;
    float wy1 = iy - fy0, wy0 = 1.0f - wy1;

    float vx0 = (x0  >= 0 && x0  < WW) ? 1.0f : 0.0f;
    float vx1 = (x1i >= 0 && x1i < WW) ? 1.0f : 0.0f;
    float vy0 = (y0  >= 0 && y0  < HH) ? 1.0f : 0.0f;
    float vy1 = (y1i >= 0 && y1i < HH) ? 1.0f : 0.0f;

    int x0c = min(max(x0,  0), WW - 1);
    int x1c = min(max(x1i, 0), WW - 1);
    int y0c = min(max(y0,  0), HH - 1);
    int y1c = min(max(y1i, 0), HH - 1);

    float w00 = wy0 * wx0 * vy0 * vx0;
    float w01 = wy0 * wx1 * vy0 * vx1;
    float w10 = wy1 * wx0 * vy1 * vx0;
    float w11 = wy1 * wx1 * vy1 * vx1;

    int off00 = y0c * WW + x0c;
    int off01 = y0c * WW + x1c;
    int off10 = y1c * WW + x0c;
    int off11 = y1c * WW + x1c;

    const int plane = HH * WW;                       // 25600
    const float* f0 = feat + ((size_t)b * CC + cp) * plane;

    float acc[CPT];
    #pragma unroll
    for (int j = 0; j < CPT; j++) {
        const float* fc = f0 + (size_t)j * CPART * plane;
        float v00 = __ldg(fc + off00);
        float v01 = __ldg(fc + off01);
        float v10 = __ldg(fc + off10);
        float v11 = __ldg(fc + off11);
        acc[j] = w00 * v00 + w01 * v01 + w10 * v10 + w11 * v11;
    }

    float* o = out + ((size_t)k * CC + cp) * (OH * OW) + oy * OW + ox;
    #pragma unroll
    for (int j = 0; j < CPT; j++) {
        o[(size_t)j * CPART * OH * OW] = acc[j];
    }
}

extern "C" void kernel_launch(void* const* d_in, const int* in_sizes, int n_in,
                              void* d_out, int out_size)
{
    const float* feat = (const float*)d_in[0];
    const float* rois = (const float*)d_in[1];
    float* out = (float*)d_out;

    int K = in_sizes[1] / 5;                 // 1024
    if (K > MAXK) K = MAXK;

    roi_sort_kernel<<<1, 256>>>(rois, K);

    int total = K * CPART * OH * OW;         // each thread does CPT channels
    int threads = 256;
    int blocks = (total + threads - 1) / threads;
    DynamicRoIAlign_52913997087012_kernel<<<blocks, threads>>>(feat, rois, out, total);
}